// round 2
// baseline (speedup 1.0000x reference)
#include <cuda_runtime.h>
#include <math.h>
#include <stdint.h>

// ---------------------------------------------------------------------------
// AngleLinear (SphereFace A-Softmax forward, m=4, it=1)
//   out[n,c] = clip( (x_n . w_c) / (|x_n| * |w_c|), -1, 1 ) * |x_n|
//   out[n, target[n]] += (phi(c_t) - c_t) * |x_n| / (1 + lambda)
// lambda = 1500/1.1, phi(c) = sign * (8c^4 - 8c^2 + 1) - 2k,
// k = floor(4*acos(c)/pi), sign = (-1)^k
// ---------------------------------------------------------------------------

#define PI_F 3.141592653f
// 1 / (1 + 1500/1.1), folded from doubles
#define INVL ((float)(1.0 / (1.0 + 1500.0 / 1.1)))

__device__ float g_wnorm[100352];
__device__ float g_xnorm[1024];

// ---- packed f32x2 helpers (Blackwell FFMA2 path) --------------------------
__device__ __forceinline__ unsigned long long pk2(float lo, float hi) {
    unsigned long long r;
    asm("mov.b64 %0, {%1, %2};" : "=l"(r) : "f"(lo), "f"(hi));
    return r;
}
__device__ __forceinline__ void upk2(unsigned long long v, float& lo, float& hi) {
    asm("mov.b64 {%0, %1}, %2;" : "=f"(lo), "=f"(hi) : "l"(v));
}
__device__ __forceinline__ void ffma2(unsigned long long& d,
                                      unsigned long long a,
                                      unsigned long long b) {
    asm("fma.rn.f32x2 %0, %1, %2, %0;" : "+l"(d) : "l"(a), "l"(b));
}

// ---- column norms of weight [D, C] (axis 0) --------------------------------
__global__ void wnorm_kernel(const float* __restrict__ W, int D, int C) {
    int c = blockIdx.x * blockDim.x + threadIdx.x;
    if (c >= C) return;
    float s = 0.0f;
#pragma unroll 8
    for (int d = 0; d < D; d++) {
        float v = __ldg(&W[(size_t)d * C + c]);
        s = fmaf(v, v, s);
    }
    g_wnorm[c] = sqrtf(s);
}

// ---- row norms of x [N, D] (axis 1) ----------------------------------------
__global__ void xnorm_kernel(const float* __restrict__ X, int N, int D) {
    int warp = (blockIdx.x * blockDim.x + threadIdx.x) >> 5;
    int lane = threadIdx.x & 31;
    if (warp >= N) return;
    float s = 0.0f;
    for (int d = lane; d < D; d += 32) {
        float v = X[(size_t)warp * D + d];
        s = fmaf(v, v, s);
    }
#pragma unroll
    for (int o = 16; o > 0; o >>= 1) s += __shfl_down_sync(0xffffffffu, s, o);
    if (lane == 0) g_xnorm[warp] = sqrtf(s);
}

// ---- epilogue per element ---------------------------------------------------
__device__ __forceinline__ float epi_elem(float v, float rxn, float xn,
                                          float rwn, int c, long long tgt) {
    float cc = v * rxn * rwn;
    cc = fminf(1.0f, fmaxf(-1.0f, cc));
    float o = cc * xn;
    if ((long long)c == tgt) {
        float c2 = cc * cc;
        float cosm = fmaf(8.0f * c2, c2, fmaf(-8.0f, c2, 1.0f));  // 8c^4-8c^2+1
        float th = acosf(cc);
        float kf = floorf(th * (4.0f / PI_F));
        int ki = (int)kf;
        float sgn = (ki & 1) ? -1.0f : 1.0f;
        float phi = fmaf(sgn, cosm, -2.0f * kf);
        o += (phi - cc) * xn * INVL;
    }
    return o;
}

// ---- main GEMM + epilogue ---------------------------------------------------
// BM=128, BN=128, BK=16, 256 threads, 8x8 microtile per thread.
// Thread t: tx = t%16 (N dir), ty = t/16 (M dir).
//   rows:    m0 + ty + 16*i           (i = 0..7)
//   columns: c0 + 2*tx + 32*j + {0,1} (j = 0..3, adjacent pairs for f32x2)
__global__ void __launch_bounds__(256, 2)
gemm_epi_kernel(const float* __restrict__ X, const float* __restrict__ W,
                const long long* __restrict__ TGT, float* __restrict__ OUT,
                int N, int D, int C) {
    __shared__ float As[128][17];   // [m][k], pad 17 kills phase conflicts
    __shared__ float Bs[16][128];   // [k][c]

    const int tid = threadIdx.x;
    const int tx = tid & 15;
    const int ty = tid >> 4;
    const int m0 = blockIdx.y * 128;
    const int c0 = blockIdx.x * 128;

    unsigned long long acc[8][4];
#pragma unroll
    for (int i = 0; i < 8; i++)
#pragma unroll
        for (int j = 0; j < 4; j++) acc[i][j] = 0ULL;

    for (int k0 = 0; k0 < D; k0 += 16) {
        // load A tile (128 x 16), coalesced along k
#pragma unroll
        for (int i = 0; i < 8; i++) {
            int e = tid + 256 * i;
            int m = e >> 4, k = e & 15;
            int gm = m0 + m;
            As[m][k] = (gm < N) ? X[(size_t)gm * D + (k0 + k)] : 0.0f;
        }
        // load B tile (16 x 128), coalesced along c
#pragma unroll
        for (int i = 0; i < 8; i++) {
            int e = tid + 256 * i;
            int k = e >> 7, c = e & 127;
            int gc = c0 + c;
            Bs[k][c] = (gc < C) ? W[(size_t)(k0 + k) * C + gc] : 0.0f;
        }
        __syncthreads();

#pragma unroll
        for (int k = 0; k < 16; k++) {
            unsigned long long a2[8], b2[4];
#pragma unroll
            for (int i = 0; i < 8; i++) {
                float a = As[ty + 16 * i][k];
                a2[i] = pk2(a, a);
            }
#pragma unroll
            for (int j = 0; j < 4; j++) {
                float2 b = *reinterpret_cast<const float2*>(&Bs[k][2 * tx + 32 * j]);
                b2[j] = pk2(b.x, b.y);
            }
#pragma unroll
            for (int i = 0; i < 8; i++)
#pragma unroll
                for (int j = 0; j < 4; j++) ffma2(acc[i][j], a2[i], b2[j]);
        }
        __syncthreads();
    }

    // ---- epilogue ----
    float xn[8], rxn[8];
    long long tg[8];
#pragma unroll
    for (int i = 0; i < 8; i++) {
        int row = m0 + ty + 16 * i;
        if (row < N) {
            xn[i] = g_xnorm[row];
            rxn[i] = 1.0f / xn[i];
            tg[i] = TGT[row];
        } else {
            xn[i] = 1.0f; rxn[i] = 1.0f; tg[i] = -1;
        }
    }

#pragma unroll
    for (int j = 0; j < 4; j++) {
        int c = c0 + 2 * tx + 32 * j;
        if (c >= C) continue;  // C is even -> pair fully valid or fully not
        float rw0 = 1.0f / g_wnorm[c];
        float rw1 = 1.0f / g_wnorm[c + 1];
#pragma unroll
        for (int i = 0; i < 8; i++) {
            int row = m0 + ty + 16 * i;
            if (row >= N) continue;
            float v0, v1;
            upk2(acc[i][j], v0, v1);
            float2 o;
            o.x = epi_elem(v0, rxn[i], xn[i], rw0, c, tg[i]);
            o.y = epi_elem(v1, rxn[i], xn[i], rw1, c + 1, tg[i]);
            *reinterpret_cast<float2*>(&OUT[(size_t)row * C + c]) = o;
        }
    }
}

// ---------------------------------------------------------------------------
extern "C" void kernel_launch(void* const* d_in, const int* in_sizes, int n_in,
                              void* d_out, int out_size) {
    const float* x = (const float*)d_in[0];
    const long long* tgt = (const long long*)d_in[1];
    const float* w = (const float*)d_in[2];
    float* out = (float*)d_out;

    const int N = in_sizes[1];            // 512
    const int D = in_sizes[0] / N;        // 512
    const int C = in_sizes[2] / D;        // 100000

    xnorm_kernel<<<(N + 7) / 8, 256>>>(x, N, D);
    wnorm_kernel<<<(C + 255) / 256, 256>>>(w, D, C);

    dim3 grid((C + 127) / 128, (N + 127) / 128);
    gemm_epi_kernel<<<grid, 256>>>(x, w, tgt, out, N, D, C);
}